// round 14
// baseline (speedup 1.0000x reference)
#include <cuda_runtime.h>
#include <cuda_fp16.h>
#include <cstdint>

#define NB   8
#define SEQ  1024
#define DM   512
#define NH   8
#define HD   64
#define MROWS (NB*SEQ)   // 8192
#define NQKV 1536        // fused QKV output width

#define QSCALE 0.18033688f   // 0.125 * log2(e): folded into Wq/bq; attn uses ex2

// fp16 scratch (device globals: no allocation allowed)
__device__ __align__(16) __half g_x[(size_t)MROWS*DM];        // nodes fp16
__device__ __align__(16) __half g_wqkv[(size_t)DM*NQKV];      // Wq|Wk|Wv fp16 [k][n] (Wq pre-scaled)
__device__ __align__(16) __half g_wo[(size_t)DM*DM];          // Wo fp16 [k][n]
__device__ __align__(16) __half g_q[(size_t)NB*NH*SEQ*HD];
__device__ __align__(16) __half g_k[(size_t)NB*NH*SEQ*HD];
__device__ __align__(16) __half g_v[(size_t)NB*NH*SEQ*HD];
__device__ __align__(16) __half g_m[(size_t)MROWS*DM];

// ---------------------------------------------------------------------------
// helpers
// ---------------------------------------------------------------------------
__device__ __forceinline__ uint32_t sm_u32(const void* p) {
    return (uint32_t)__cvta_generic_to_shared(p);
}
__device__ __forceinline__ uint32_t h2pack(float a, float b) {
    __half2 h = __floats2half2_rn(a, b);
    return *(uint32_t*)&h;
}
__device__ __forceinline__ float ex2(float x) {
    float y;
    asm("ex2.approx.ftz.f32 %0, %1;" : "=f"(y) : "f"(x));
    return y;
}
__device__ __forceinline__ void ldm4(uint32_t* r, uint32_t a) {
    asm volatile("ldmatrix.sync.aligned.m8n8.x4.shared.b16 {%0,%1,%2,%3}, [%4];"
        : "=r"(r[0]), "=r"(r[1]), "=r"(r[2]), "=r"(r[3]) : "r"(a));
}
__device__ __forceinline__ void ldm4t(uint32_t* r, uint32_t a) {
    asm volatile("ldmatrix.sync.aligned.m8n8.x4.trans.shared.b16 {%0,%1,%2,%3}, [%4];"
        : "=r"(r[0]), "=r"(r[1]), "=r"(r[2]), "=r"(r[3]) : "r"(a));
}
__device__ __forceinline__ void mma16(float* d, const uint32_t* a,
                                      uint32_t b0, uint32_t b1) {
    asm volatile(
        "mma.sync.aligned.m16n8k16.row.col.f32.f16.f16.f32 "
        "{%0,%1,%2,%3}, {%4,%5,%6,%7}, {%8,%9}, {%0,%1,%2,%3};"
        : "+f"(d[0]), "+f"(d[1]), "+f"(d[2]), "+f"(d[3])
        : "r"(a[0]), "r"(a[1]), "r"(a[2]), "r"(a[3]), "r"(b0), "r"(b1));
}
__device__ __forceinline__ void cpasync16(uint32_t dst, const void* src) {
    asm volatile("cp.async.cg.shared.global [%0], [%1], 16;" :: "r"(dst), "l"(src));
}
__device__ __forceinline__ void cpcommit() {
    asm volatile("cp.async.commit_group;" ::: "memory");
}

// ---------------------------------------------------------------------------
// One-shot fp32 -> fp16 conversion / packing. Wq (z==0) pre-scaled by QSCALE.
// ---------------------------------------------------------------------------
__global__ void convert_kernel(
    const float* __restrict__ nodes,
    const float* __restrict__ Wq, const float* __restrict__ Wk,
    const float* __restrict__ Wv, const float* __restrict__ Wo)
{
    const size_t N1 = (size_t)MROWS * DM / 4;   // g_x
    const size_t N2 = (size_t)DM * NQKV / 4;    // g_wqkv
    const size_t N3 = (size_t)DM * DM / 4;      // g_wo
    const size_t total = N1 + N2 + N3;
    for (size_t i = (size_t)blockIdx.x * blockDim.x + threadIdx.x;
         i < total; i += (size_t)gridDim.x * blockDim.x) {
        if (i < N1) {
            float4 v = ((const float4*)nodes)[i];
            uint2 p = {h2pack(v.x, v.y), h2pack(v.z, v.w)};
            ((uint2*)g_x)[i] = p;
        } else if (i < N1 + N2) {
            const size_t j = i - N1;           // over [DM][NQKV/4]
            const int k = (int)(j / (NQKV / 4));
            const int c4 = (int)(j % (NQKV / 4));
            const int c = c4 * 4;
            const int z = c >> 9, n = c & 511;
            const float* W = (z == 0) ? Wq : (z == 1 ? Wk : Wv);
            const float sc = (z == 0) ? QSCALE : 1.0f;
            float4 v = *(const float4*)(W + (size_t)k * DM + n);
            uint2 p = {h2pack(v.x * sc, v.y * sc), h2pack(v.z * sc, v.w * sc)};
            ((uint2*)g_wqkv)[j] = p;
        } else {
            const size_t j = i - N1 - N2;
            float4 v = ((const float4*)Wo)[j];
            uint2 p = {h2pack(v.x, v.y), h2pack(v.z, v.w)};
            ((uint2*)g_wo)[j] = p;
        }
    }
}

// ---------------------------------------------------------------------------
// GEMM tiling: CTA 128x128, BK=32, 256 threads (8 warps 2x4, warp 64x32),
// 3-stage cp.async, ONE barrier per K-step. 64x32 warp tile: each B fragment
// feeds 4 m-tiles -> 25% less smem read traffic per MAC vs 32x32 warps.
// ---------------------------------------------------------------------------
#define SA  40    // A tile stride in halfs (32 + 8)
#define SB  136   // B tile stride in halfs (128 + 8)
#define ASZ (128*SA)
#define BSZ (32*SB)
#define STG_A (ASZ*2)  // bytes
#define STG_B (BSZ*2)
#define GEMM_SMEM (3 * (STG_A + STG_B))   // 56,832 bytes

// ---------------------------------------------------------------------------
// Fused QKV GEMM: g_x[8192,512] @ g_wqkv[512,1536] -> head-major fp16 q/k/v.
// grid = (12, 64), 256 threads
// ---------------------------------------------------------------------------
__global__ __launch_bounds__(256, 2) void qkv_gemm(
    const float* __restrict__ bq, const float* __restrict__ bk,
    const float* __restrict__ bv)
{
    extern __shared__ __align__(16) __half dynsh[];
    __half* As = dynsh;
    __half* Bs = dynsh + 3 * ASZ;

    const int tid  = threadIdx.x;
    const int lane = tid & 31;
    const int wid  = tid >> 5;
    const int wm   = wid >> 2;   // 0..1 (64-row halves)
    const int wn   = wid & 3;    // 0..3 (32-col quarters)
    const int g    = lane >> 2;
    const int a4   = lane & 3;
    const int row0 = blockIdx.y << 7;
    const int col0 = blockIdx.x << 7;

    const uint32_t aB = sm_u32(As), bB = sm_u32(Bs);

    auto ISSUE = [&](int s) {
        const int k0 = s * 32;
        const uint32_t ad = aB + (s % 3) * STG_A;
        const uint32_t bd = bB + (s % 3) * STG_B;
        #pragma unroll
        for (int i = 0; i < 2; ++i) {
            const int idx = tid + i * 256;
            const int r = idx >> 2, c = (idx & 3) << 3;
            cpasync16(ad + (r * SA + c) * 2,
                      g_x + (size_t)(row0 + r) * DM + k0 + c);
        }
        #pragma unroll
        for (int i = 0; i < 2; ++i) {
            const int idx = tid + i * 256;
            const int r = idx >> 4, c = (idx & 15) << 3;
            cpasync16(bd + (r * SB + c) * 2,
                      g_wqkv + (size_t)(k0 + r) * NQKV + col0 + c);
        }
        cpcommit();
    };

    ISSUE(0); ISSUE(1);

    float acc[16][4] = {};

    for (int s = 0; s < 16; ++s) {
        if (s < 14) asm volatile("cp.async.wait_group 1;" ::: "memory");
        else        asm volatile("cp.async.wait_group 0;" ::: "memory");
        __syncthreads();   // stage s visible; all warps done with stage s-1
        if (s + 2 < 16) ISSUE(s + 2);   // overwrites buffer (s-1)%3 -- safe

        const uint32_t ab = aB + (s % 3) * STG_A;
        const uint32_t bb = bB + (s % 3) * STG_B;
        #pragma unroll
        for (int kc = 0; kc < 2; ++kc) {
            uint32_t af[4][4], bf[2][4];
            #pragma unroll
            for (int mf = 0; mf < 4; ++mf) {
                const int r = wm * 64 + mf * 16 + (lane & 15);
                const int c = kc * 16 + ((lane >> 4) << 3);
                ldm4(af[mf], ab + (r * SA + c) * 2);
            }
            #pragma unroll
            for (int np = 0; np < 2; ++np) {
                const int r = kc * 16 + (lane & 15);
                const int c = wn * 32 + np * 16 + ((lane >> 4) << 3);
                ldm4t(bf[np], bb + (r * SB + c) * 2);
            }
            #pragma unroll
            for (int mf = 0; mf < 4; ++mf)
                #pragma unroll
                for (int np = 0; np < 2; ++np) {
                    mma16(acc[mf * 4 + np * 2 + 0], af[mf], bf[np][0], bf[np][1]);
                    mma16(acc[mf * 4 + np * 2 + 1], af[mf], bf[np][2], bf[np][3]);
                }
        }
    }

    // epilogue: decode z/head, add fp32 bias (bq pre-scaled), head-major fp16
    const int z = col0 >> 9;
    const float* bias = (z == 0) ? bq : (z == 1 ? bk : bv);
    const float bscale = (z == 0) ? QSCALE : 1.0f;
    __half* outp = (z == 0) ? g_q : (z == 1 ? g_k : g_v);
    #pragma unroll
    for (int mf = 0; mf < 4; ++mf)
        #pragma unroll
        for (int nf = 0; nf < 4; ++nf) {
            const int r = row0 + wm * 64 + mf * 16 + g;
            const int c = col0 + wn * 32 + nf * 8 + 2 * a4;
            const int rem = c & 511;
            const int h = rem >> 6, d = rem & 63;
            const float b0 = bias[rem] * bscale, b1 = bias[rem + 1] * bscale;
            const float* ac = acc[mf * 4 + nf];
            {
                const int bb_ = r >> 10, sr = r & (SEQ - 1);
                *(uint32_t*)&outp[(((size_t)bb_ * NH + h) * SEQ + sr) * HD + d] =
                    h2pack(ac[0] + b0, ac[1] + b1);
            }
            {
                const int r2 = r + 8, bb_ = r2 >> 10, sr = r2 & (SEQ - 1);
                *(uint32_t*)&outp[(((size_t)bb_ * NH + h) * SEQ + sr) * HD + d] =
                    h2pack(ac[2] + b0, ac[3] + b1);
            }
        }
}

// ---------------------------------------------------------------------------
// Output projection: g_m[8192,512] @ g_wo[512,512] + bo -> fp32 out.
// grid = (4, 64), 256 threads
// ---------------------------------------------------------------------------
__global__ __launch_bounds__(256, 2) void out_gemm(
    const float* __restrict__ bo, float* __restrict__ Cout)
{
    extern __shared__ __align__(16) __half dynsh[];
    __half* As = dynsh;
    __half* Bs = dynsh + 3 * ASZ;

    const int tid  = threadIdx.x;
    const int lane = tid & 31;
    const int wid  = tid >> 5;
    const int wm   = wid >> 2;
    const int wn   = wid & 3;
    const int g    = lane >> 2;
    const int a4   = lane & 3;
    const int row0 = blockIdx.y << 7;
    const int col0 = blockIdx.x << 7;

    const uint32_t aB = sm_u32(As), bB = sm_u32(Bs);

    auto ISSUE = [&](int s) {
        const int k0 = s * 32;
        const uint32_t ad = aB + (s % 3) * STG_A;
        const uint32_t bd = bB + (s % 3) * STG_B;
        #pragma unroll
        for (int i = 0; i < 2; ++i) {
            const int idx = tid + i * 256;
            const int r = idx >> 2, c = (idx & 3) << 3;
            cpasync16(ad + (r * SA + c) * 2,
                      g_m + (size_t)(row0 + r) * DM + k0 + c);
        }
        #pragma unroll
        for (int i = 0; i < 2; ++i) {
            const int idx = tid + i * 256;
            const int r = idx >> 4, c = (idx & 15) << 3;
            cpasync16(bd + (r * SB + c) * 2,
                      g_wo + (size_t)(k0 + r) * DM + col0 + c);
        }
        cpcommit();
    };

    ISSUE(0); ISSUE(1);

    float acc[16][4] = {};

    for (int s = 0; s < 16; ++s) {
        if (s < 14) asm volatile("cp.async.wait_group 1;" ::: "memory");
        else        asm volatile("cp.async.wait_group 0;" ::: "memory");
        __syncthreads();
        if (s + 2 < 16) ISSUE(s + 2);

        const uint32_t ab = aB + (s % 3) * STG_A;
        const uint32_t bb = bB + (s % 3) * STG_B;
        #pragma unroll
        for (int kc = 0; kc < 2; ++kc) {
            uint32_t af[4][4], bf[2][4];
            #pragma unroll
            for (int mf = 0; mf < 4; ++mf) {
                const int r = wm * 64 + mf * 16 + (lane & 15);
                const int c = kc * 16 + ((lane >> 4) << 3);
                ldm4(af[mf], ab + (r * SA + c) * 2);
            }
            #pragma unroll
            for (int np = 0; np < 2; ++np) {
                const int r = kc * 16 + (lane & 15);
                const int c = wn * 32 + np * 16 + ((lane >> 4) << 3);
                ldm4t(bf[np], bb + (r * SB + c) * 2);
            }
            #pragma unroll
            for (int mf = 0; mf < 4; ++mf)
                #pragma unroll
                for (int np = 0; np < 2; ++np) {
                    mma16(acc[mf * 4 + np * 2 + 0], af[mf], bf[np][0], bf[np][1]);
                    mma16(acc[mf * 4 + np * 2 + 1], af[mf], bf[np][2], bf[np][3]);
                }
        }
    }

    #pragma unroll
    for (int mf = 0; mf < 4; ++mf)
        #pragma unroll
        for (int nf = 0; nf < 4; ++nf) {
            const int r = row0 + wm * 64 + mf * 16 + g;
            const int c = col0 + wn * 32 + nf * 8 + 2 * a4;
            const float b0 = bo[c], b1 = bo[c + 1];
            const float* ac = acc[mf * 4 + nf];
            float2 o0 = {ac[0] + b0, ac[1] + b1};
            *(float2*)(Cout + (size_t)r * DM + c) = o0;
            float2 o1 = {ac[2] + b0, ac[3] + b1};
            *(float2*)(Cout + (size_t)(r + 8) * DM + c) = o1;
        }
}

// ---------------------------------------------------------------------------
// Flash attention (exact R9 config -- best measured): fp16 mma.sync, 128 Q
// rows/CTA, KV 64-row tiles, 3-buffer cp.async ring, no online max (QSCALE
// folded into Q projection; p = 2^S via scalar ex2), row sums via tensor
// core (ones-column B fragment). grid = (8, 64), 256 threads.
// ---------------------------------------------------------------------------
#define SK   72
#define KVSZ (64 * SK)                      // halfs per K or V tile
#define ATTN_SMEM (6 * KVSZ * 2)            // 55,296 bytes (3 KV buffer pairs)

__global__ __launch_bounds__(256, 2) void attn_kernel()
{
    extern __shared__ __align__(16) __half ash[];

    const int tid  = threadIdx.x;
    const int lane = tid & 31;
    const int wid  = tid >> 5;
    const int g    = lane >> 2;
    const int a4   = lane & 3;
    const int b    = blockIdx.y >> 3;
    const int h    = blockIdx.y & 7;
    const int q0   = blockIdx.x << 7;

    const __half* Qg = g_q + (size_t)(b * NH + h) * SEQ * HD;
    const __half* Kg = g_k + (size_t)(b * NH + h) * SEQ * HD;
    const __half* Vg = g_v + (size_t)(b * NH + h) * SEQ * HD;
    const uint32_t shB = sm_u32(ash);

    // Q tile -> smem -> register fragments (Q already carries QSCALE)
    #pragma unroll
    for (int i = 0; i < 4; ++i) {
        const int idx = tid + i * 256, r = idx >> 3, c = (idx & 7) << 3;
        *(uint4*)&ash[r * SK + c] = *(const uint4*)(Qg + (size_t)(q0 + r) * HD + c);
    }
    __syncthreads();
    uint32_t qa[4][4];
    #pragma unroll
    for (int kc = 0; kc < 4; ++kc) {
        const int r = wid * 16 + (lane & 15);
        const int c = kc * 16 + ((lane >> 4) << 3);
        ldm4(qa[kc], shB + (r * SK + c) * 2);
    }
    __syncthreads();

    auto ISSUE = [&](int t) {
        const int buf = t % 3;
        const __half* Ksrc = Kg + (size_t)t * 64 * HD;
        const __half* Vsrc = Vg + (size_t)t * 64 * HD;
        const uint32_t kd = shB + (buf * 2 * KVSZ) * 2;
        const uint32_t vd = kd + KVSZ * 2;
        #pragma unroll
        for (int i = 0; i < 2; ++i) {
            const int idx = tid + i * 256, r = idx >> 3, c = (idx & 7) << 3;
            cpasync16(kd + (r * SK + c) * 2, Ksrc + (size_t)r * HD + c);
            cpasync16(vd + (r * SK + c) * 2, Vsrc + (size_t)r * HD + c);
        }
        cpcommit();
    };

    ISSUE(0); ISSUE(1);

    // ones-column B fragment: column 0 of an n8 group = 1.0 (lanes g==0)
    const uint32_t ones = (g == 0) ? 0x3C003C00u : 0u;

    float o[8][4] = {};
    float la[4] = {};   // la[0]: row-g sum (lanes a4==0); la[2]: row g+8

    for (int t = 0; t < 16; ++t) {
        if (t < 15) asm volatile("cp.async.wait_group 1;" ::: "memory");
        else        asm volatile("cp.async.wait_group 0;" ::: "memory");
        __syncthreads();
        if (t + 2 < 16) ISSUE(t + 2);

        const uint32_t kb = shB + ((t % 3) * 2 * KVSZ) * 2;
        const uint32_t vb = kb + KVSZ * 2;

        // S = Q K^T  (16 x 64 per warp)
        float s[8][4] = {};
        #pragma unroll
        for (int kc = 0; kc < 4; ++kc) {
            #pragma unroll
            for (int np = 0; np < 4; ++np) {
                uint32_t bf[4];
                const int r = np * 16 + (lane & 15);
                const int c = kc * 16 + ((lane >> 4) << 3);
                ldm4(bf, kb + (r * SK + c) * 2);
                mma16(s[np * 2 + 0], qa[kc], bf[0], bf[2]);
                mma16(s[np * 2 + 1], qa[kc], bf[1], bf[3]);
            }
        }

        // p = 2^s (scale pre-folded); repack accumulator -> A-fragment
        uint32_t pa[4][4];
        #pragma unroll
        for (int kc = 0; kc < 4; ++kc) {
            pa[kc][0] = h2pack(ex2(s[2*kc][0]),   ex2(s[2*kc][1]));
            pa[kc][1] = h2pack(ex2(s[2*kc][2]),   ex2(s[2*kc][3]));
            pa[kc][2] = h2pack(ex2(s[2*kc+1][0]), ex2(s[2*kc+1][1]));
            pa[kc][3] = h2pack(ex2(s[2*kc+1][2]), ex2(s[2*kc+1][3]));
        }

        // O += P V ; la += P @ ones (row sums on the tensor pipe)
        #pragma unroll
        for (int kc = 0; kc < 4; ++kc) {
            mma16(la, pa[kc], ones, ones);
            #pragma unroll
            for (int np = 0; np < 4; ++np) {
                uint32_t bf[4];
                const int r = kc * 16 + (lane & 15);
                const int c = np * 16 + ((lane >> 4) << 3);
                ldm4t(bf, vb + (r * SK + c) * 2);
                mma16(o[np * 2 + 0], pa[kc], bf[0], bf[1]);
                mma16(o[np * 2 + 1], pa[kc], bf[2], bf[3]);
            }
        }
    }

    // fetch row sums (live in lanes a4==0, i.e., lane g*4) and normalize
    const float l0 = __shfl_sync(0xffffffffu, la[0], g << 2);
    const float l1 = __shfl_sync(0xffffffffu, la[2], g << 2);
    const float inv0 = 1.0f / l0, inv1 = 1.0f / l1;
    __half* Mg = g_m + (size_t)b * SEQ * DM + (size_t)h * HD;
    const int r0 = q0 + wid * 16 + g, r1 = r0 + 8;
    #pragma unroll
    for (int nf = 0; nf < 8; ++nf) {
        const int d = nf * 8 + 2 * a4;
        *(uint32_t*)(Mg + (size_t)r0 * DM + d) = h2pack(o[nf][0] * inv0, o[nf][1] * inv0);
        *(uint32_t*)(Mg + (size_t)r1 * DM + d) = h2pack(o[nf][2] * inv1, o[nf][3] * inv1);
    }
}

// ---------------------------------------------------------------------------
extern "C" void kernel_launch(void* const* d_in, const int* in_sizes, int n_in,
                              void* d_out, int out_size)
{
    (void)in_sizes; (void)n_in; (void)out_size;
    const float* nodes = (const float*)d_in[0];
    const float* Wq = (const float*)d_in[1];
    const float* Wk = (const float*)d_in[2];
    const float* Wv = (const float*)d_in[3];
    const float* bq = (const float*)d_in[4];
    const float* bk = (const float*)d_in[5];
    const float* bv = (const float*)d_in[6];
    const float* Wo = (const float*)d_in[7];
    const float* bo = (const float*)d_in[8];
    float* out = (float*)d_out;

    cudaFuncSetAttribute(qkv_gemm,
                         cudaFuncAttributeMaxDynamicSharedMemorySize, GEMM_SMEM);
    cudaFuncSetAttribute(out_gemm,
                         cudaFuncAttributeMaxDynamicSharedMemorySize, GEMM_SMEM);
    cudaFuncSetAttribute(attn_kernel,
                         cudaFuncAttributeMaxDynamicSharedMemorySize, ATTN_SMEM);

    convert_kernel<<<1184, 256>>>(nodes, Wq, Wk, Wv, Wo);
    qkv_gemm<<<dim3(NQKV / 128, MROWS / 128), 256, GEMM_SMEM>>>(bq, bk, bv);
    attn_kernel<<<dim3(SEQ / 128, NB * NH), 256, ATTN_SMEM>>>();
    out_gemm<<<dim3(DM / 128, MROWS / 128), 256, GEMM_SMEM>>>(bo, out);
}

// round 15
// speedup vs baseline: 1.0549x; 1.0549x over previous
#include <cuda_runtime.h>
#include <cuda_fp16.h>
#include <cstdint>

#define NB   8
#define SEQ  1024
#define DM   512
#define NH   8
#define HD   64
#define MROWS (NB*SEQ)   // 8192
#define NQKV 1536        // fused QKV output width

#define QSCALE 0.18033688f   // 0.125 * log2(e): folded into Wq/bq; attn uses ex2

// fp16 scratch (device globals: no allocation allowed)
__device__ __align__(16) __half g_x[(size_t)MROWS*DM];        // nodes fp16
__device__ __align__(16) __half g_wqkv[(size_t)DM*NQKV];      // Wq|Wk|Wv fp16 [k][n] (Wq pre-scaled)
__device__ __align__(16) __half g_wo[(size_t)DM*DM];          // Wo fp16 [k][n]
__device__ __align__(16) __half g_q[(size_t)NB*NH*SEQ*HD];
__device__ __align__(16) __half g_k[(size_t)NB*NH*SEQ*HD];
__device__ __align__(16) __half g_v[(size_t)NB*NH*SEQ*HD];
__device__ __align__(16) __half g_m[(size_t)MROWS*DM];

// ---------------------------------------------------------------------------
// helpers
// ---------------------------------------------------------------------------
__device__ __forceinline__ uint32_t sm_u32(const void* p) {
    return (uint32_t)__cvta_generic_to_shared(p);
}
__device__ __forceinline__ uint32_t h2pack(float a, float b) {
    __half2 h = __floats2half2_rn(a, b);
    return *(uint32_t*)&h;
}
__device__ __forceinline__ float ex2(float x) {
    float y;
    asm("ex2.approx.ftz.f32 %0, %1;" : "=f"(y) : "f"(x));
    return y;
}
__device__ __forceinline__ void ldm4(uint32_t* r, uint32_t a) {
    asm volatile("ldmatrix.sync.aligned.m8n8.x4.shared.b16 {%0,%1,%2,%3}, [%4];"
        : "=r"(r[0]), "=r"(r[1]), "=r"(r[2]), "=r"(r[3]) : "r"(a));
}
__device__ __forceinline__ void ldm4t(uint32_t* r, uint32_t a) {
    asm volatile("ldmatrix.sync.aligned.m8n8.x4.trans.shared.b16 {%0,%1,%2,%3}, [%4];"
        : "=r"(r[0]), "=r"(r[1]), "=r"(r[2]), "=r"(r[3]) : "r"(a));
}
__device__ __forceinline__ void mma16(float* d, const uint32_t* a,
                                      uint32_t b0, uint32_t b1) {
    asm volatile(
        "mma.sync.aligned.m16n8k16.row.col.f32.f16.f16.f32 "
        "{%0,%1,%2,%3}, {%4,%5,%6,%7}, {%8,%9}, {%0,%1,%2,%3};"
        : "+f"(d[0]), "+f"(d[1]), "+f"(d[2]), "+f"(d[3])
        : "r"(a[0]), "r"(a[1]), "r"(a[2]), "r"(a[3]), "r"(b0), "r"(b1));
}
__device__ __forceinline__ void cpasync16(uint32_t dst, const void* src) {
    asm volatile("cp.async.cg.shared.global [%0], [%1], 16;" :: "r"(dst), "l"(src));
}
__device__ __forceinline__ void cpcommit() {
    asm volatile("cp.async.commit_group;" ::: "memory");
}

// ---------------------------------------------------------------------------
// One-shot fp32 -> fp16 conversion / packing. Wq (z==0) pre-scaled by QSCALE.
// ---------------------------------------------------------------------------
__global__ void convert_kernel(
    const float* __restrict__ nodes,
    const float* __restrict__ Wq, const float* __restrict__ Wk,
    const float* __restrict__ Wv, const float* __restrict__ Wo)
{
    const size_t N1 = (size_t)MROWS * DM / 4;   // g_x
    const size_t N2 = (size_t)DM * NQKV / 4;    // g_wqkv
    const size_t N3 = (size_t)DM * DM / 4;      // g_wo
    const size_t total = N1 + N2 + N3;
    for (size_t i = (size_t)blockIdx.x * blockDim.x + threadIdx.x;
         i < total; i += (size_t)gridDim.x * blockDim.x) {
        if (i < N1) {
            float4 v = ((const float4*)nodes)[i];
            uint2 p = {h2pack(v.x, v.y), h2pack(v.z, v.w)};
            ((uint2*)g_x)[i] = p;
        } else if (i < N1 + N2) {
            const size_t j = i - N1;           // over [DM][NQKV/4]
            const int k = (int)(j / (NQKV / 4));
            const int c4 = (int)(j % (NQKV / 4));
            const int c = c4 * 4;
            const int z = c >> 9, n = c & 511;
            const float* W = (z == 0) ? Wq : (z == 1 ? Wk : Wv);
            const float sc = (z == 0) ? QSCALE : 1.0f;
            float4 v = *(const float4*)(W + (size_t)k * DM + n);
            uint2 p = {h2pack(v.x * sc, v.y * sc), h2pack(v.z * sc, v.w * sc)};
            ((uint2*)g_wqkv)[j] = p;
        } else {
            const size_t j = i - N1 - N2;
            float4 v = ((const float4*)Wo)[j];
            uint2 p = {h2pack(v.x, v.y), h2pack(v.z, v.w)};
            ((uint2*)g_wo)[j] = p;
        }
    }
}

// ---------------------------------------------------------------------------
// GEMM tiling: CTA 128x128, BK=64, 512 threads (16 warps 4x4, warp 32x32),
// 3-stage cp.async, ONE barrier per K-step (8 barriers; 32 warp-MMAs each).
// ---------------------------------------------------------------------------
#define SA  72    // A tile stride in halfs (64 + 8)
#define SB  136   // B tile stride in halfs (128 + 8)
#define ASZ (128*SA)
#define BSZ (64*SB)
#define STG_A (ASZ*2)  // 18432 bytes
#define STG_B (BSZ*2)  // 17408 bytes
#define GEMM_SMEM (3 * (STG_A + STG_B))   // 107,520 bytes

// ---------------------------------------------------------------------------
// Fused QKV GEMM: g_x[8192,512] @ g_wqkv[512,1536] -> head-major fp16 q/k/v.
// grid = (12, 64), 512 threads
// ---------------------------------------------------------------------------
__global__ __launch_bounds__(512, 2) void qkv_gemm(
    const float* __restrict__ bq, const float* __restrict__ bk,
    const float* __restrict__ bv)
{
    extern __shared__ __align__(16) __half dynsh[];
    __half* As = dynsh;
    __half* Bs = dynsh + 3 * ASZ;

    const int tid  = threadIdx.x;
    const int lane = tid & 31;
    const int wid  = tid >> 5;
    const int wm   = wid >> 2;   // 0..3
    const int wn   = wid & 3;    // 0..3
    const int g    = lane >> 2;
    const int a4   = lane & 3;
    const int row0 = blockIdx.y << 7;
    const int col0 = blockIdx.x << 7;

    const uint32_t aB = sm_u32(As), bB = sm_u32(Bs);

    auto ISSUE = [&](int s) {
        const int k0 = s * 64;
        const uint32_t ad = aB + (s % 3) * STG_A;
        const uint32_t bd = bB + (s % 3) * STG_B;
        #pragma unroll
        for (int i = 0; i < 2; ++i) {
            const int idx = tid + i * 512;
            const int r = idx >> 3, c = (idx & 7) << 3;
            cpasync16(ad + (r * SA + c) * 2,
                      g_x + (size_t)(row0 + r) * DM + k0 + c);
        }
        #pragma unroll
        for (int i = 0; i < 2; ++i) {
            const int idx = tid + i * 512;
            const int r = idx >> 4, c = (idx & 15) << 3;
            cpasync16(bd + (r * SB + c) * 2,
                      g_wqkv + (size_t)(k0 + r) * NQKV + col0 + c);
        }
        cpcommit();
    };

    ISSUE(0); ISSUE(1);

    float acc[8][4] = {};

    for (int s = 0; s < 8; ++s) {
        if (s < 6) asm volatile("cp.async.wait_group 1;" ::: "memory");
        else       asm volatile("cp.async.wait_group 0;" ::: "memory");
        __syncthreads();   // stage s visible; all warps done with stage s-1
        if (s + 2 < 8) ISSUE(s + 2);   // overwrites buffer (s-1)%3 -- safe

        const uint32_t ab = aB + (s % 3) * STG_A;
        const uint32_t bb = bB + (s % 3) * STG_B;
        #pragma unroll
        for (int kc = 0; kc < 4; ++kc) {
            uint32_t af[2][4], bf[2][4];
            #pragma unroll
            for (int mf = 0; mf < 2; ++mf) {
                const int r = wm * 32 + mf * 16 + (lane & 15);
                const int c = kc * 16 + ((lane >> 4) << 3);
                ldm4(af[mf], ab + (r * SA + c) * 2);
            }
            #pragma unroll
            for (int np = 0; np < 2; ++np) {
                const int r = kc * 16 + (lane & 15);
                const int c = wn * 32 + np * 16 + ((lane >> 4) << 3);
                ldm4t(bf[np], bb + (r * SB + c) * 2);
            }
            #pragma unroll
            for (int mf = 0; mf < 2; ++mf)
                #pragma unroll
                for (int np = 0; np < 2; ++np) {
                    mma16(acc[mf * 4 + np * 2 + 0], af[mf], bf[np][0], bf[np][1]);
                    mma16(acc[mf * 4 + np * 2 + 1], af[mf], bf[np][2], bf[np][3]);
                }
        }
    }

    // epilogue: decode z/head, add fp32 bias (bq pre-scaled), head-major fp16
    const int z = col0 >> 9;
    const float* bias = (z == 0) ? bq : (z == 1 ? bk : bv);
    const float bscale = (z == 0) ? QSCALE : 1.0f;
    __half* outp = (z == 0) ? g_q : (z == 1 ? g_k : g_v);
    #pragma unroll
    for (int mf = 0; mf < 2; ++mf)
        #pragma unroll
        for (int nf = 0; nf < 4; ++nf) {
            const int r = row0 + wm * 32 + mf * 16 + g;
            const int c = col0 + wn * 32 + nf * 8 + 2 * a4;
            const int rem = c & 511;
            const int h = rem >> 6, d = rem & 63;
            const float b0 = bias[rem] * bscale, b1 = bias[rem + 1] * bscale;
            const float* ac = acc[mf * 4 + nf];
            {
                const int bb_ = r >> 10, sr = r & (SEQ - 1);
                *(uint32_t*)&outp[(((size_t)bb_ * NH + h) * SEQ + sr) * HD + d] =
                    h2pack(ac[0] + b0, ac[1] + b1);
            }
            {
                const int r2 = r + 8, bb_ = r2 >> 10, sr = r2 & (SEQ - 1);
                *(uint32_t*)&outp[(((size_t)bb_ * NH + h) * SEQ + sr) * HD + d] =
                    h2pack(ac[2] + b0, ac[3] + b1);
            }
        }
}

// ---------------------------------------------------------------------------
// Output projection: g_m[8192,512] @ g_wo[512,512] + bo -> fp32 out.
// grid = (4, 64), 512 threads
// ---------------------------------------------------------------------------
__global__ __launch_bounds__(512, 2) void out_gemm(
    const float* __restrict__ bo, float* __restrict__ Cout)
{
    extern __shared__ __align__(16) __half dynsh[];
    __half* As = dynsh;
    __half* Bs = dynsh + 3 * ASZ;

    const int tid  = threadIdx.x;
    const int lane = tid & 31;
    const int wid  = tid >> 5;
    const int wm   = wid >> 2;
    const int wn   = wid & 3;
    const int g    = lane >> 2;
    const int a4   = lane & 3;
    const int row0 = blockIdx.y << 7;
    const int col0 = blockIdx.x << 7;

    const uint32_t aB = sm_u32(As), bB = sm_u32(Bs);

    auto ISSUE = [&](int s) {
        const int k0 = s * 64;
        const uint32_t ad = aB + (s % 3) * STG_A;
        const uint32_t bd = bB + (s % 3) * STG_B;
        #pragma unroll
        for (int i = 0; i < 2; ++i) {
            const int idx = tid + i * 512;
            const int r = idx >> 3, c = (idx & 7) << 3;
            cpasync16(ad + (r * SA + c) * 2,
                      g_m + (size_t)(row0 + r) * DM + k0 + c);
        }
        #pragma unroll
        for (int i = 0; i < 2; ++i) {
            const int idx = tid + i * 512;
            const int r = idx >> 4, c = (idx & 15) << 3;
            cpasync16(bd + (r * SB + c) * 2,
                      g_wo + (size_t)(k0 + r) * DM + col0 + c);
        }
        cpcommit();
    };

    ISSUE(0); ISSUE(1);

    float acc[8][4] = {};

    for (int s = 0; s < 8; ++s) {
        if (s < 6) asm volatile("cp.async.wait_group 1;" ::: "memory");
        else       asm volatile("cp.async.wait_group 0;" ::: "memory");
        __syncthreads();
        if (s + 2 < 8) ISSUE(s + 2);

        const uint32_t ab = aB + (s % 3) * STG_A;
        const uint32_t bb = bB + (s % 3) * STG_B;
        #pragma unroll
        for (int kc = 0; kc < 4; ++kc) {
            uint32_t af[2][4], bf[2][4];
            #pragma unroll
            for (int mf = 0; mf < 2; ++mf) {
                const int r = wm * 32 + mf * 16 + (lane & 15);
                const int c = kc * 16 + ((lane >> 4) << 3);
                ldm4(af[mf], ab + (r * SA + c) * 2);
            }
            #pragma unroll
            for (int np = 0; np < 2; ++np) {
                const int r = kc * 16 + (lane & 15);
                const int c = wn * 32 + np * 16 + ((lane >> 4) << 3);
                ldm4t(bf[np], bb + (r * SB + c) * 2);
            }
            #pragma unroll
            for (int mf = 0; mf < 2; ++mf)
                #pragma unroll
                for (int np = 0; np < 2; ++np) {
                    mma16(acc[mf * 4 + np * 2 + 0], af[mf], bf[np][0], bf[np][1]);
                    mma16(acc[mf * 4 + np * 2 + 1], af[mf], bf[np][2], bf[np][3]);
                }
        }
    }

    #pragma unroll
    for (int mf = 0; mf < 2; ++mf)
        #pragma unroll
        for (int nf = 0; nf < 4; ++nf) {
            const int r = row0 + wm * 32 + mf * 16 + g;
            const int c = col0 + wn * 32 + nf * 8 + 2 * a4;
            const float b0 = bo[c], b1 = bo[c + 1];
            const float* ac = acc[mf * 4 + nf];
            float2 o0 = {ac[0] + b0, ac[1] + b1};
            *(float2*)(Cout + (size_t)r * DM + c) = o0;
            float2 o1 = {ac[2] + b0, ac[3] + b1};
            *(float2*)(Cout + (size_t)(r + 8) * DM + c) = o1;
        }
}

// ---------------------------------------------------------------------------
// Flash attention (exact R9 config -- best measured): fp16 mma.sync, 128 Q
// rows/CTA, KV 64-row tiles, 3-buffer cp.async ring, no online max (QSCALE
// folded into Q projection; p = 2^S via scalar ex2), row sums via tensor
// core (ones-column B fragment). grid = (8, 64), 256 threads.
// ---------------------------------------------------------------------------
#define SK   72
#define KVSZ (64 * SK)                      // halfs per K or V tile
#define ATTN_SMEM (6 * KVSZ * 2)            // 55,296 bytes (3 KV buffer pairs)

__global__ __launch_bounds__(256, 2) void attn_kernel()
{
    extern __shared__ __align__(16) __half ash[];

    const int tid  = threadIdx.x;
    const int lane = tid & 31;
    const int wid  = tid >> 5;
    const int g    = lane >> 2;
    const int a4   = lane & 3;
    const int b    = blockIdx.y >> 3;
    const int h    = blockIdx.y & 7;
    const int q0   = blockIdx.x << 7;

    const __half* Qg = g_q + (size_t)(b * NH + h) * SEQ * HD;
    const __half* Kg = g_k + (size_t)(b * NH + h) * SEQ * HD;
    const __half* Vg = g_v + (size_t)(b * NH + h) * SEQ * HD;
    const uint32_t shB = sm_u32(ash);

    // Q tile -> smem -> register fragments (Q already carries QSCALE)
    #pragma unroll
    for (int i = 0; i < 4; ++i) {
        const int idx = tid + i * 256, r = idx >> 3, c = (idx & 7) << 3;
        *(uint4*)&ash[r * SK + c] = *(const uint4*)(Qg + (size_t)(q0 + r) * HD + c);
    }
    __syncthreads();
    uint32_t qa[4][4];
    #pragma unroll
    for (int kc = 0; kc < 4; ++kc) {
        const int r = wid * 16 + (lane & 15);
        const int c = kc * 16 + ((lane >> 4) << 3);
        ldm4(qa[kc], shB + (r * SK + c) * 2);
    }
    __syncthreads();

    auto ISSUE = [&](int t) {
        const int buf = t % 3;
        const __half* Ksrc = Kg + (size_t)t * 64 * HD;
        const __half* Vsrc = Vg + (size_t)t * 64 * HD;
        const uint32_t kd = shB + (buf * 2 * KVSZ) * 2;
        const uint32_t vd = kd + KVSZ * 2;
        #pragma unroll
        for (int i = 0; i < 2; ++i) {
            const int idx = tid + i * 256, r = idx >> 3, c = (idx & 7) << 3;
            cpasync16(kd + (r * SK + c) * 2, Ksrc + (size_t)r * HD + c);
            cpasync16(vd + (r * SK + c) * 2, Vsrc + (size_t)r * HD + c);
        }
        cpcommit();
    };

    ISSUE(0); ISSUE(1);

    // ones-column B fragment: column 0 of an n8 group = 1.0 (lanes g==0)
    const uint32_t ones = (g == 0) ? 0x3C003C00u : 0u;

    float o[8][4] = {};
    float la[4] = {};   // la[0]: row-g sum (lanes a4==0); la[2]: row g+8

    for (int t = 0; t < 16; ++t) {
        if (t < 15) asm volatile("cp.async.wait_group 1;" ::: "memory");
        else        asm volatile("cp.async.wait_group 0;" ::: "memory");
        __syncthreads();
        if (t + 2 < 16) ISSUE(t + 2);

        const uint32_t kb = shB + ((t % 3) * 2 * KVSZ) * 2;
        const uint32_t vb = kb + KVSZ * 2;

        // S = Q K^T  (16 x 64 per warp)
        float s[8][4] = {};
        #pragma unroll
        for (int kc = 0; kc < 4; ++kc) {
            #pragma unroll
            for (int np = 0; np < 4; ++np) {
                uint32_t bf[4];
                const int r = np * 16 + (lane & 15);
                const int c = kc * 16 + ((lane >> 4) << 3);
                ldm4(bf, kb + (r * SK + c) * 2);
                mma16(s[np * 2 + 0], qa[kc], bf[0], bf[2]);
                mma16(s[np * 2 + 1], qa[kc], bf[1], bf[3]);
            }
        }

        // p = 2^s (scale pre-folded); repack accumulator -> A-fragment
        uint32_t pa[4][4];
        #pragma unroll
        for (int kc = 0; kc < 4; ++kc) {
            pa[kc][0] = h2pack(ex2(s[2*kc][0]),   ex2(s[2*kc][1]));
            pa[kc][1] = h2pack(ex2(s[2*kc][2]),   ex2(s[2*kc][3]));
            pa[kc][2] = h2pack(ex2(s[2*kc+1][0]), ex2(s[2*kc+1][1]));
            pa[kc][3] = h2pack(ex2(s[2*kc+1][2]), ex2(s[2*kc+1][3]));
        }

        // O += P V ; la += P @ ones (row sums on the tensor pipe)
        #pragma unroll
        for (int kc = 0; kc < 4; ++kc) {
            mma16(la, pa[kc], ones, ones);
            #pragma unroll
            for (int np = 0; np < 4; ++np) {
                uint32_t bf[4];
                const int r = kc * 16 + (lane & 15);
                const int c = np * 16 + ((lane >> 4) << 3);
                ldm4t(bf, vb + (r * SK + c) * 2);
                mma16(o[np * 2 + 0], pa[kc], bf[0], bf[1]);
                mma16(o[np * 2 + 1], pa[kc], bf[2], bf[3]);
            }
        }
    }

    // fetch row sums (live in lanes a4==0, i.e., lane g*4) and normalize
    const float l0 = __shfl_sync(0xffffffffu, la[0], g << 2);
    const float l1 = __shfl_sync(0xffffffffu, la[2], g << 2);
    const float inv0 = 1.0f / l0, inv1 = 1.0f / l1;
    __half* Mg = g_m + (size_t)b * SEQ * DM + (size_t)h * HD;
    const int r0 = q0 + wid * 16 + g, r1 = r0 + 8;
    #pragma unroll
    for (int nf = 0; nf < 8; ++nf) {
        const int d = nf * 8 + 2 * a4;
        *(uint32_t*)(Mg + (size_t)r0 * DM + d) = h2pack(o[nf][0] * inv0, o[nf][1] * inv0);
        *(uint32_t*)(Mg + (size_t)r1 * DM + d) = h2pack(o[nf][2] * inv1, o[nf][3] * inv1);
    }
}

// ---------------------------------------------------------------------------
extern "C" void kernel_launch(void* const* d_in, const int* in_sizes, int n_in,
                              void* d_out, int out_size)
{
    (void)in_sizes; (void)n_in; (void)out_size;
    const float* nodes = (const float*)d_in[0];
    const float* Wq = (const float*)d_in[1];
    const float* Wk = (const float*)d_in[2];
    const float* Wv = (const float*)d_in[3];
    const float* bq = (const float*)d_in[4];
    const float* bk = (const float*)d_in[5];
    const float* bv = (const float*)d_in[6];
    const float* Wo = (const float*)d_in[7];
    const float* bo = (const float*)d_in[8];
    float* out = (float*)d_out;

    cudaFuncSetAttribute(qkv_gemm,
                         cudaFuncAttributeMaxDynamicSharedMemorySize, GEMM_SMEM);
    cudaFuncSetAttribute(out_gemm,
                         cudaFuncAttributeMaxDynamicSharedMemorySize, GEMM_SMEM);
    cudaFuncSetAttribute(attn_kernel,
                         cudaFuncAttributeMaxDynamicSharedMemorySize, ATTN_SMEM);

    convert_kernel<<<1184, 256>>>(nodes, Wq, Wk, Wv, Wo);
    qkv_gemm<<<dim3(NQKV / 128, MROWS / 128), 512, GEMM_SMEM>>>(bq, bk, bv);
    attn_kernel<<<dim3(SEQ / 128, NB * NH), 256, ATTN_SMEM>>>();
    out_gemm<<<dim3(DM / 128, MROWS / 128), 512, GEMM_SMEM>>>(bo, out);
}

// round 16
// speedup vs baseline: 1.0691x; 1.0135x over previous
#include <cuda_runtime.h>
#include <cuda_fp16.h>
#include <cstdint>

#define NB   8
#define SEQ  1024
#define DM   512
#define NH   8
#define HD   64
#define MROWS (NB*SEQ)   // 8192
#define NQKV 1536        // fused QKV output width

#define QSCALE 0.18033688f   // 0.125 * log2(e): folded into Wq/bq; attn uses ex2

// fp16 scratch (device globals: no allocation allowed)
__device__ __align__(16) __half g_x[(size_t)MROWS*DM];        // nodes fp16
__device__ __align__(16) __half g_wqkv[(size_t)DM*NQKV];      // Wq|Wk|Wv fp16 [k][n] (Wq pre-scaled)
__device__ __align__(16) __half g_wo[(size_t)DM*DM];          // Wo fp16 [k][n]
__device__ __align__(16) __half g_q[(size_t)NB*NH*SEQ*HD];
__device__ __align__(16) __half g_k[(size_t)NB*NH*SEQ*HD];
__device__ __align__(16) __half g_v[(size_t)NB*NH*SEQ*HD];
__device__ __align__(16) __half g_m[(size_t)MROWS*DM];

// ---------------------------------------------------------------------------
// helpers
// ---------------------------------------------------------------------------
__device__ __forceinline__ uint32_t sm_u32(const void* p) {
    return (uint32_t)__cvta_generic_to_shared(p);
}
__device__ __forceinline__ uint32_t h2pack(float a, float b) {
    __half2 h = __floats2half2_rn(a, b);
    return *(uint32_t*)&h;
}
__device__ __forceinline__ float ex2(float x) {
    float y;
    asm("ex2.approx.ftz.f32 %0, %1;" : "=f"(y) : "f"(x));
    return y;
}
__device__ __forceinline__ void ldm4(uint32_t* r, uint32_t a) {
    asm volatile("ldmatrix.sync.aligned.m8n8.x4.shared.b16 {%0,%1,%2,%3}, [%4];"
        : "=r"(r[0]), "=r"(r[1]), "=r"(r[2]), "=r"(r[3]) : "r"(a));
}
__device__ __forceinline__ void ldm4t(uint32_t* r, uint32_t a) {
    asm volatile("ldmatrix.sync.aligned.m8n8.x4.trans.shared.b16 {%0,%1,%2,%3}, [%4];"
        : "=r"(r[0]), "=r"(r[1]), "=r"(r[2]), "=r"(r[3]) : "r"(a));
}
__device__ __forceinline__ void mma16(float* d, const uint32_t* a,
                                      uint32_t b0, uint32_t b1) {
    asm volatile(
        "mma.sync.aligned.m16n8k16.row.col.f32.f16.f16.f32 "
        "{%0,%1,%2,%3}, {%4,%5,%6,%7}, {%8,%9}, {%0,%1,%2,%3};"
        : "+f"(d[0]), "+f"(d[1]), "+f"(d[2]), "+f"(d[3])
        : "r"(a[0]), "r"(a[1]), "r"(a[2]), "r"(a[3]), "r"(b0), "r"(b1));
}
__device__ __forceinline__ void cpasync16(uint32_t dst, const void* src) {
    asm volatile("cp.async.cg.shared.global [%0], [%1], 16;" :: "r"(dst), "l"(src));
}
__device__ __forceinline__ void cpcommit() {
    asm volatile("cp.async.commit_group;" ::: "memory");
}

// ---------------------------------------------------------------------------
// One-shot fp32 -> fp16 conversion / packing. Wq (z==0) pre-scaled by QSCALE.
// ---------------------------------------------------------------------------
__global__ void convert_kernel(
    const float* __restrict__ nodes,
    const float* __restrict__ Wq, const float* __restrict__ Wk,
    const float* __restrict__ Wv, const float* __restrict__ Wo)
{
    const size_t N1 = (size_t)MROWS * DM / 4;   // g_x
    const size_t N2 = (size_t)DM * NQKV / 4;    // g_wqkv
    const size_t N3 = (size_t)DM * DM / 4;      // g_wo
    const size_t total = N1 + N2 + N3;
    for (size_t i = (size_t)blockIdx.x * blockDim.x + threadIdx.x;
         i < total; i += (size_t)gridDim.x * blockDim.x) {
        if (i < N1) {
            float4 v = ((const float4*)nodes)[i];
            uint2 p = {h2pack(v.x, v.y), h2pack(v.z, v.w)};
            ((uint2*)g_x)[i] = p;
        } else if (i < N1 + N2) {
            const size_t j = i - N1;           // over [DM][NQKV/4]
            const int k = (int)(j / (NQKV / 4));
            const int c4 = (int)(j % (NQKV / 4));
            const int c = c4 * 4;
            const int z = c >> 9, n = c & 511;
            const float* W = (z == 0) ? Wq : (z == 1 ? Wk : Wv);
            const float sc = (z == 0) ? QSCALE : 1.0f;
            float4 v = *(const float4*)(W + (size_t)k * DM + n);
            uint2 p = {h2pack(v.x * sc, v.y * sc), h2pack(v.z * sc, v.w * sc)};
            ((uint2*)g_wqkv)[j] = p;
        } else {
            const size_t j = i - N1 - N2;
            float4 v = ((const float4*)Wo)[j];
            uint2 p = {h2pack(v.x, v.y), h2pack(v.z, v.w)};
            ((uint2*)g_wo)[j] = p;
        }
    }
}

// ---------------------------------------------------------------------------
// GEMM tiling (frozen R15 config): CTA 128x128, BK=64, 512 threads (16 warps
// 4x4, warp 32x32), 3-stage cp.async, ONE barrier per K-step.
// ---------------------------------------------------------------------------
#define SA  72    // A tile stride in halfs (64 + 8)
#define SB  136   // B tile stride in halfs (128 + 8)
#define ASZ (128*SA)
#define BSZ (64*SB)
#define STG_A (ASZ*2)  // 18432 bytes
#define STG_B (BSZ*2)  // 17408 bytes
#define GEMM_SMEM (3 * (STG_A + STG_B))   // 107,520 bytes

// ---------------------------------------------------------------------------
// Fused QKV GEMM: g_x[8192,512] @ g_wqkv[512,1536] -> head-major fp16 q/k/v.
// grid = (12, 64), 512 threads
// ---------------------------------------------------------------------------
__global__ __launch_bounds__(512, 2) void qkv_gemm(
    const float* __restrict__ bq, const float* __restrict__ bk,
    const float* __restrict__ bv)
{
    extern __shared__ __align__(16) __half dynsh[];
    __half* As = dynsh;
    __half* Bs = dynsh + 3 * ASZ;

    const int tid  = threadIdx.x;
    const int lane = tid & 31;
    const int wid  = tid >> 5;
    const int wm   = wid >> 2;   // 0..3
    const int wn   = wid & 3;    // 0..3
    const int g    = lane >> 2;
    const int a4   = lane & 3;
    const int row0 = blockIdx.y << 7;
    const int col0 = blockIdx.x << 7;

    const uint32_t aB = sm_u32(As), bB = sm_u32(Bs);

    auto ISSUE = [&](int s) {
        const int k0 = s * 64;
        const uint32_t ad = aB + (s % 3) * STG_A;
        const uint32_t bd = bB + (s % 3) * STG_B;
        #pragma unroll
        for (int i = 0; i < 2; ++i) {
            const int idx = tid + i * 512;
            const int r = idx >> 3, c = (idx & 7) << 3;
            cpasync16(ad + (r * SA + c) * 2,
                      g_x + (size_t)(row0 + r) * DM + k0 + c);
        }
        #pragma unroll
        for (int i = 0; i < 2; ++i) {
            const int idx = tid + i * 512;
            const int r = idx >> 4, c = (idx & 15) << 3;
            cpasync16(bd + (r * SB + c) * 2,
                      g_wqkv + (size_t)(k0 + r) * NQKV + col0 + c);
        }
        cpcommit();
    };

    ISSUE(0); ISSUE(1);

    float acc[8][4] = {};

    for (int s = 0; s < 8; ++s) {
        if (s < 6) asm volatile("cp.async.wait_group 1;" ::: "memory");
        else       asm volatile("cp.async.wait_group 0;" ::: "memory");
        __syncthreads();   // stage s visible; all warps done with stage s-1
        if (s + 2 < 8) ISSUE(s + 2);   // overwrites buffer (s-1)%3 -- safe

        const uint32_t ab = aB + (s % 3) * STG_A;
        const uint32_t bb = bB + (s % 3) * STG_B;
        #pragma unroll
        for (int kc = 0; kc < 4; ++kc) {
            uint32_t af[2][4], bf[2][4];
            #pragma unroll
            for (int mf = 0; mf < 2; ++mf) {
                const int r = wm * 32 + mf * 16 + (lane & 15);
                const int c = kc * 16 + ((lane >> 4) << 3);
                ldm4(af[mf], ab + (r * SA + c) * 2);
            }
            #pragma unroll
            for (int np = 0; np < 2; ++np) {
                const int r = kc * 16 + (lane & 15);
                const int c = wn * 32 + np * 16 + ((lane >> 4) << 3);
                ldm4t(bf[np], bb + (r * SB + c) * 2);
            }
            #pragma unroll
            for (int mf = 0; mf < 2; ++mf)
                #pragma unroll
                for (int np = 0; np < 2; ++np) {
                    mma16(acc[mf * 4 + np * 2 + 0], af[mf], bf[np][0], bf[np][1]);
                    mma16(acc[mf * 4 + np * 2 + 1], af[mf], bf[np][2], bf[np][3]);
                }
        }
    }

    // epilogue: decode z/head, add fp32 bias (bq pre-scaled), head-major fp16
    const int z = col0 >> 9;
    const float* bias = (z == 0) ? bq : (z == 1 ? bk : bv);
    const float bscale = (z == 0) ? QSCALE : 1.0f;
    __half* outp = (z == 0) ? g_q : (z == 1 ? g_k : g_v);
    #pragma unroll
    for (int mf = 0; mf < 2; ++mf)
        #pragma unroll
        for (int nf = 0; nf < 4; ++nf) {
            const int r = row0 + wm * 32 + mf * 16 + g;
            const int c = col0 + wn * 32 + nf * 8 + 2 * a4;
            const int rem = c & 511;
            const int h = rem >> 6, d = rem & 63;
            const float b0 = bias[rem] * bscale, b1 = bias[rem + 1] * bscale;
            const float* ac = acc[mf * 4 + nf];
            {
                const int bb_ = r >> 10, sr = r & (SEQ - 1);
                *(uint32_t*)&outp[(((size_t)bb_ * NH + h) * SEQ + sr) * HD + d] =
                    h2pack(ac[0] + b0, ac[1] + b1);
            }
            {
                const int r2 = r + 8, bb_ = r2 >> 10, sr = r2 & (SEQ - 1);
                *(uint32_t*)&outp[(((size_t)bb_ * NH + h) * SEQ + sr) * HD + d] =
                    h2pack(ac[2] + b0, ac[3] + b1);
            }
        }
}

// ---------------------------------------------------------------------------
// Output projection: g_m[8192,512] @ g_wo[512,512] + bo -> fp32 out.
// grid = (4, 64), 512 threads
// ---------------------------------------------------------------------------
__global__ __launch_bounds__(512, 2) void out_gemm(
    const float* __restrict__ bo, float* __restrict__ Cout)
{
    extern __shared__ __align__(16) __half dynsh[];
    __half* As = dynsh;
    __half* Bs = dynsh + 3 * ASZ;

    const int tid  = threadIdx.x;
    const int lane = tid & 31;
    const int wid  = tid >> 5;
    const int wm   = wid >> 2;
    const int wn   = wid & 3;
    const int g    = lane >> 2;
    const int a4   = lane & 3;
    const int row0 = blockIdx.y << 7;
    const int col0 = blockIdx.x << 7;

    const uint32_t aB = sm_u32(As), bB = sm_u32(Bs);

    auto ISSUE = [&](int s) {
        const int k0 = s * 64;
        const uint32_t ad = aB + (s % 3) * STG_A;
        const uint32_t bd = bB + (s % 3) * STG_B;
        #pragma unroll
        for (int i = 0; i < 2; ++i) {
            const int idx = tid + i * 512;
            const int r = idx >> 3, c = (idx & 7) << 3;
            cpasync16(ad + (r * SA + c) * 2,
                      g_m + (size_t)(row0 + r) * DM + k0 + c);
        }
        #pragma unroll
        for (int i = 0; i < 2; ++i) {
            const int idx = tid + i * 512;
            const int r = idx >> 4, c = (idx & 15) << 3;
            cpasync16(bd + (r * SB + c) * 2,
                      g_wo + (size_t)(k0 + r) * DM + col0 + c);
        }
        cpcommit();
    };

    ISSUE(0); ISSUE(1);

    float acc[8][4] = {};

    for (int s = 0; s < 8; ++s) {
        if (s < 6) asm volatile("cp.async.wait_group 1;" ::: "memory");
        else       asm volatile("cp.async.wait_group 0;" ::: "memory");
        __syncthreads();
        if (s + 2 < 8) ISSUE(s + 2);

        const uint32_t ab = aB + (s % 3) * STG_A;
        const uint32_t bb = bB + (s % 3) * STG_B;
        #pragma unroll
        for (int kc = 0; kc < 4; ++kc) {
            uint32_t af[2][4], bf[2][4];
            #pragma unroll
            for (int mf = 0; mf < 2; ++mf) {
                const int r = wm * 32 + mf * 16 + (lane & 15);
                const int c = kc * 16 + ((lane >> 4) << 3);
                ldm4(af[mf], ab + (r * SA + c) * 2);
            }
            #pragma unroll
            for (int np = 0; np < 2; ++np) {
                const int r = kc * 16 + (lane & 15);
                const int c = wn * 32 + np * 16 + ((lane >> 4) << 3);
                ldm4t(bf[np], bb + (r * SB + c) * 2);
            }
            #pragma unroll
            for (int mf = 0; mf < 2; ++mf)
                #pragma unroll
                for (int np = 0; np < 2; ++np) {
                    mma16(acc[mf * 4 + np * 2 + 0], af[mf], bf[np][0], bf[np][1]);
                    mma16(acc[mf * 4 + np * 2 + 1], af[mf], bf[np][2], bf[np][3]);
                }
        }
    }

    #pragma unroll
    for (int mf = 0; mf < 2; ++mf)
        #pragma unroll
        for (int nf = 0; nf < 4; ++nf) {
            const int r = row0 + wm * 32 + mf * 16 + g;
            const int c = col0 + wn * 32 + nf * 8 + 2 * a4;
            const float b0 = bo[c], b1 = bo[c + 1];
            const float* ac = acc[mf * 4 + nf];
            float2 o0 = {ac[0] + b0, ac[1] + b1};
            *(float2*)(Cout + (size_t)r * DM + c) = o0;
            float2 o1 = {ac[2] + b0, ac[3] + b1};
            *(float2*)(Cout + (size_t)(r + 8) * DM + c) = o1;
        }
}

// ---------------------------------------------------------------------------
// Flash attention: fp16 mma.sync, 128 Q rows/CTA, KV tiles of 128 rows
// processed as two independent 64-row halves (no barrier between halves --
// softmax is shift-free so halves just accumulate). 2-buffer cp.async double
// buffer, prefetch issued after barrier BEFORE compute (full overlap).
// 8 barriers/CTA instead of 16. p = 2^S via scalar ex2 (QSCALE pre-folded),
// row sums via tensor core. grid = (8, 64), 256 threads.
// ---------------------------------------------------------------------------
#define SK      72
#define TILE128 (128 * SK)                  // halfs per K or V 128-row tile
#define ATTN_SMEM (2 * 2 * TILE128 * 2)     // 73,728 bytes (2 buffers x K,V)

__global__ __launch_bounds__(256, 2) void attn_kernel()
{
    extern __shared__ __align__(16) __half ash[];

    const int tid  = threadIdx.x;
    const int lane = tid & 31;
    const int wid  = tid >> 5;
    const int g    = lane >> 2;
    const int a4   = lane & 3;
    const int b    = blockIdx.y >> 3;
    const int h    = blockIdx.y & 7;
    const int q0   = blockIdx.x << 7;

    const __half* Qg = g_q + (size_t)(b * NH + h) * SEQ * HD;
    const __half* Kg = g_k + (size_t)(b * NH + h) * SEQ * HD;
    const __half* Vg = g_v + (size_t)(b * NH + h) * SEQ * HD;
    const uint32_t shB = sm_u32(ash);

    // Q tile -> smem -> register fragments (Q already carries QSCALE)
    #pragma unroll
    for (int i = 0; i < 4; ++i) {
        const int idx = tid + i * 256, r = idx >> 3, c = (idx & 7) << 3;
        *(uint4*)&ash[r * SK + c] = *(const uint4*)(Qg + (size_t)(q0 + r) * HD + c);
    }
    __syncthreads();
    uint32_t qa[4][4];
    #pragma unroll
    for (int kc = 0; kc < 4; ++kc) {
        const int r = wid * 16 + (lane & 15);
        const int c = kc * 16 + ((lane >> 4) << 3);
        ldm4(qa[kc], shB + (r * SK + c) * 2);
    }
    __syncthreads();

    // Load one 128-row K tile + 128-row V tile into buffer (t&1).
    auto ISSUE = [&](int t) {
        const __half* Ksrc = Kg + (size_t)t * 128 * HD;
        const __half* Vsrc = Vg + (size_t)t * 128 * HD;
        const uint32_t kd = shB + ((t & 1) * 2 * TILE128) * 2;
        const uint32_t vd = kd + TILE128 * 2;
        #pragma unroll
        for (int i = 0; i < 4; ++i) {
            const int idx = tid + i * 256, r = idx >> 3, c = (idx & 7) << 3;
            cpasync16(kd + (r * SK + c) * 2, Ksrc + (size_t)r * HD + c);
            cpasync16(vd + (r * SK + c) * 2, Vsrc + (size_t)r * HD + c);
        }
        cpcommit();
    };

    ISSUE(0);

    // ones-column B fragment: column 0 of an n8 group = 1.0 (lanes g==0)
    const uint32_t ones = (g == 0) ? 0x3C003C00u : 0u;

    float o[8][4] = {};
    float la[4] = {};   // la[0]: row-g sum (lanes a4==0); la[2]: row g+8

    for (int t = 0; t < 8; ++t) {
        asm volatile("cp.async.wait_group 0;" ::: "memory");  // tile t landed
        __syncthreads();   // all warps done with buffer (t-1)&1 == (t+1)&1
        if (t + 1 < 8) ISSUE(t + 1);   // load next tile during compute

        const uint32_t kb = shB + ((t & 1) * 2 * TILE128) * 2;
        const uint32_t vb = kb + TILE128 * 2;

        #pragma unroll
        for (int half = 0; half < 2; ++half) {
            const uint32_t kbh = kb + (half * 64 * SK) * 2;
            const uint32_t vbh = vb + (half * 64 * SK) * 2;

            // S = Q K^T  (16 x 64 per warp)
            float s[8][4] = {};
            #pragma unroll
            for (int kc = 0; kc < 4; ++kc) {
                #pragma unroll
                for (int np = 0; np < 4; ++np) {
                    uint32_t bf[4];
                    const int r = np * 16 + (lane & 15);
                    const int c = kc * 16 + ((lane >> 4) << 3);
                    ldm4(bf, kbh + (r * SK + c) * 2);
                    mma16(s[np * 2 + 0], qa[kc], bf[0], bf[2]);
                    mma16(s[np * 2 + 1], qa[kc], bf[1], bf[3]);
                }
            }

            // p = 2^s (scale pre-folded); repack accumulator -> A-fragment
            uint32_t pa[4][4];
            #pragma unroll
            for (int kc = 0; kc < 4; ++kc) {
                pa[kc][0] = h2pack(ex2(s[2*kc][0]),   ex2(s[2*kc][1]));
                pa[kc][1] = h2pack(ex2(s[2*kc][2]),   ex2(s[2*kc][3]));
                pa[kc][2] = h2pack(ex2(s[2*kc+1][0]), ex2(s[2*kc+1][1]));
                pa[kc][3] = h2pack(ex2(s[2*kc+1][2]), ex2(s[2*kc+1][3]));
            }

            // O += P V ; la += P @ ones (row sums on the tensor pipe)
            #pragma unroll
            for (int kc = 0; kc < 4; ++kc) {
                mma16(la, pa[kc], ones, ones);
                #pragma unroll
                for (int np = 0; np < 4; ++np) {
                    uint32_t bf[4];
                    const int r = kc * 16 + (lane & 15);
                    const int c = np * 16 + ((lane >> 4) << 3);
                    ldm4t(bf, vbh + (r * SK + c) * 2);
                    mma16(o[np * 2 + 0], pa[kc], bf[0], bf[1]);
                    mma16(o[np * 2 + 1], pa[kc], bf[2], bf[3]);
                }
            }
        }
    }

    // fetch row sums (live in lanes a4==0, i.e., lane g*4) and normalize
    const float l0 = __shfl_sync(0xffffffffu, la[0], g << 2);
    const float l1 = __shfl_sync(0xffffffffu, la[2], g << 2);
    const float inv0 = 1.0f / l0, inv1 = 1.0f / l1;
    __half* Mg = g_m + (size_t)b * SEQ * DM + (size_t)h * HD;
    const int r0 = q0 + wid * 16 + g, r1 = r0 + 8;
    #pragma unroll
    for (int nf = 0; nf < 8; ++nf) {
        const int d = nf * 8 + 2 * a4;
        *(uint32_t*)(Mg + (size_t)r0 * DM + d) = h2pack(o[nf][0] * inv0, o[nf][1] * inv0);
        *(uint32_t*)(Mg + (size_t)r1 * DM + d) = h2pack(o[nf][2] * inv1, o[nf][3] * inv1);
    }
}

// ---------------------------------------------------------------------------
extern "C" void kernel_launch(void* const* d_in, const int* in_sizes, int n_in,
                              void* d_out, int out_size)
{
    (void)in_sizes; (void)n_in; (void)out_size;
    const float* nodes = (const float*)d_in[0];
    const float* Wq = (const float*)d_in[1];
    const float* Wk = (const float*)d_in[2];
    const float* Wv = (const float*)d_in[3];
    const float* bq = (const float*)d_in[4];
    const float* bk = (const float*)d_in[5];
    const float* bv = (const float*)d_in[6];
    const float* Wo = (const float*)d_in[7];
    const float* bo = (const float*)d_in[8];
    float* out = (float*)d_out;

    cudaFuncSetAttribute(qkv_gemm,
                         cudaFuncAttributeMaxDynamicSharedMemorySize, GEMM_SMEM);
    cudaFuncSetAttribute(out_gemm,
                         cudaFuncAttributeMaxDynamicSharedMemorySize, GEMM_SMEM);
    cudaFuncSetAttribute(attn_kernel,
                         cudaFuncAttributeMaxDynamicSharedMemorySize, ATTN_SMEM);

    convert_kernel<<<1184, 256>>>(nodes, Wq, Wk, Wv, Wo);
    qkv_gemm<<<dim3(NQKV / 128, MROWS / 128), 512, GEMM_SMEM>>>(bq, bk, bv);
    attn_kernel<<<dim3(SEQ / 128, NB * NH), 256, ATTN_SMEM>>>();
    out_gemm<<<dim3(DM / 128, MROWS / 128), 512, GEMM_SMEM>>>(bo, out);
}